// round 1
// baseline (speedup 1.0000x reference)
#include <cuda_runtime.h>
#include <cuda_bf16.h>
#include <cstdint>

// Problem constants
#define PB 32
#define PS 1024
#define PNODE 256
#define PDEP 64
#define PR 50
#define PL 16
#define PE 128
#define PF 320           // NODE + DEP
#define EDGES_PER_LAYER (PB * PE)   // 4096

// Scratch (device globals — no allocation allowed)
__device__ float g_child[PB * PS * PDEP];           // 8.4 MB
__device__ float g_msg[PB * PE * PDEP];             // 1 MB
__device__ int   g_rsort[PL * EDGES_PER_LAYER];     // rel-sorted edge ids (b*128+e)
__device__ int   g_rel_off[PL * (PR + 1)];
__device__ int   g_hkey[PL * EDGES_PER_LAYER];      // head-sorted keys per (l,b)
__device__ int   g_hidx[PL * EDGES_PER_LAYER];      // head-sorted edge index e

// ---------------------------------------------------------------------------
// Init: copy context into out[:, :, :256] and zero g_child. float4 everywhere.
__global__ void k_init(const float* __restrict__ ctx, float* __restrict__ out) {
    const int64_t n_ctx = (int64_t)PB * PS * (PNODE / 4);   // context float4s
    const int64_t n_chd = (int64_t)PB * PS * (PDEP / 4);    // child float4s
    const int64_t total = n_ctx + n_chd;
    int64_t stride = (int64_t)gridDim.x * blockDim.x;
    for (int64_t i = (int64_t)blockIdx.x * blockDim.x + threadIdx.x; i < total; i += stride) {
        if (i < n_ctx) {
            int64_t row = i >> 6;       // / 64 float4 per row
            int64_t d4  = i & 63;
            float4 v = ((const float4*)ctx)[i];
            *(float4*)&out[row * PF + d4 * 4] = v;
        } else {
            ((float4*)g_child)[i - n_ctx] = make_float4(0.f, 0.f, 0.f, 0.f);
        }
    }
}

// ---------------------------------------------------------------------------
// Bucket edges by relation (per layer). One block per layer.
__global__ void k_bucket_rel(const int* __restrict__ rels) {
    int l = blockIdx.x;
    __shared__ int cnt[PR];
    __shared__ int off[PR];
    int tid = threadIdx.x;
    if (tid < PR) cnt[tid] = 0;
    __syncthreads();
    for (int idx = tid; idx < EDGES_PER_LAYER; idx += blockDim.x) {
        int b = idx >> 7, e = idx & 127;
        int r = rels[b * (PL * PE) + l * PE + e];
        atomicAdd(&cnt[r], 1);
    }
    __syncthreads();
    if (tid == 0) {
        int s = 0;
        for (int r = 0; r < PR; r++) {
            off[r] = s;
            g_rel_off[l * (PR + 1) + r] = s;
            s += cnt[r];
        }
        g_rel_off[l * (PR + 1) + PR] = s;
    }
    __syncthreads();
    for (int idx = tid; idx < EDGES_PER_LAYER; idx += blockDim.x) {
        int b = idx >> 7, e = idx & 127;
        int r = rels[b * (PL * PE) + l * PE + e];
        int pos = atomicAdd(&off[r], 1);
        g_rsort[l * EDGES_PER_LAYER + pos] = idx;
    }
}

// ---------------------------------------------------------------------------
// Sort edges by head per (layer, batch) via O(E^2) rank sort. Grid (L, B), 128 thr.
__global__ void k_bucket_head(const int* __restrict__ heads) {
    int l = blockIdx.x, b = blockIdx.y;
    int e = threadIdx.x;
    __shared__ int hs[PE];
    int h = heads[b * (PL * PE) + l * PE + e];
    hs[e] = h;
    __syncthreads();
    int rank = 0;
    #pragma unroll 8
    for (int o = 0; o < PE; o++) {
        int ho = hs[o];
        rank += (ho < h) || (ho == h && o < e);
    }
    int base = l * EDGES_PER_LAYER + b * PE;
    g_hkey[base + rank] = h;
    g_hidx[base + rank] = e;
}

// ---------------------------------------------------------------------------
// Message kernel: block = one (relation, 32-edge chunk). 128 threads.
// W staged transposed [d][k] stride 68 (float4-aligned, conflict-free reads),
// feats staged [32][320]. Per-thread 4e x 4k register tile, float4 d-steps.
#define CHUNK_E 32
#define WS_STRIDE 68
#define MSG_SMEM ((PF * WS_STRIDE + CHUNK_E * PF) * (int)sizeof(float))

__global__ void __launch_bounds__(128, 1)
k_msg(const float* __restrict__ ctx, const float* __restrict__ W,
      const int* __restrict__ tails, int l) {
    int r = blockIdx.x;
    int chunk = blockIdx.y;
    int off = g_rel_off[l * (PR + 1) + r];
    int end = g_rel_off[l * (PR + 1) + r + 1];
    int start = off + chunk * CHUNK_E;
    if (start >= end) return;
    int ne = min(CHUNK_E, end - start);

    extern __shared__ float sm[];
    float* Ws = sm;                      // [320][68]
    float* Fs = sm + PF * WS_STRIDE;     // [32][320]
    int tid = threadIdx.x;

    // Load W transposed: W[r][k][d] -> Ws[d*68 + k]
    const float* Wg = W + (int64_t)r * PDEP * PF;
    for (int i = tid; i < PDEP * PF; i += 128) {
        int k = i / PF, d = i - k * PF;
        Ws[d * WS_STRIDE + k] = Wg[i];
    }
    // Gather feats: context[t][0:256] ++ child[t][0:64]; zero-pad unused slots
    for (int i = tid; i < CHUNK_E * PF; i += 128) {
        int j = i / PF, d = i - j * PF;
        float v = 0.f;
        if (j < ne) {
            int edge = g_rsort[l * EDGES_PER_LAYER + start + j];
            int b = edge >> 7, e = edge & 127;
            int t = tails[b * (PL * PE) + l * PE + e];
            v = (d < PNODE) ? ctx[((int64_t)(b * PS + t)) * PNODE + d]
                            : g_child[(b * PS + t) * PDEP + (d - PNODE)];
        }
        Fs[i] = v;
    }
    __syncthreads();

    int kg = tid & 15;    // k-group: k = kg*4 .. +3
    int eg = tid >> 4;    // e-group: e = eg*4 .. +3
    float acc[4][4];
    #pragma unroll
    for (int i = 0; i < 4; i++)
        #pragma unroll
        for (int c = 0; c < 4; c++) acc[i][c] = 0.f;

    #pragma unroll 4
    for (int d = 0; d < PF; d += 4) {
        float4 w0 = *(const float4*)&Ws[(d + 0) * WS_STRIDE + kg * 4];
        float4 w1 = *(const float4*)&Ws[(d + 1) * WS_STRIDE + kg * 4];
        float4 w2 = *(const float4*)&Ws[(d + 2) * WS_STRIDE + kg * 4];
        float4 w3 = *(const float4*)&Ws[(d + 3) * WS_STRIDE + kg * 4];
        #pragma unroll
        for (int i = 0; i < 4; i++) {
            float4 f = *(const float4*)&Fs[(eg * 4 + i) * PF + d];
            acc[i][0] += f.x * w0.x; acc[i][0] += f.y * w1.x;
            acc[i][0] += f.z * w2.x; acc[i][0] += f.w * w3.x;
            acc[i][1] += f.x * w0.y; acc[i][1] += f.y * w1.y;
            acc[i][1] += f.z * w2.y; acc[i][1] += f.w * w3.y;
            acc[i][2] += f.x * w0.z; acc[i][2] += f.y * w1.z;
            acc[i][2] += f.z * w2.z; acc[i][2] += f.w * w3.z;
            acc[i][3] += f.x * w0.w; acc[i][3] += f.y * w1.w;
            acc[i][3] += f.z * w2.w; acc[i][3] += f.w * w3.w;
        }
    }

    #pragma unroll
    for (int i = 0; i < 4; i++) {
        int j = eg * 4 + i;
        if (j < ne) {
            int edge = g_rsort[l * EDGES_PER_LAYER + start + j];
            float4 o = make_float4(acc[i][0], acc[i][1], acc[i][2], acc[i][3]);
            *(float4*)&g_msg[edge * PDEP + kg * 4] = o;
        }
    }
}

// ---------------------------------------------------------------------------
// Apply: one warp per head-sorted position; segment owners average and assign.
__global__ void k_apply(int l) {
    int wid = (blockIdx.x * blockDim.x + threadIdx.x) >> 5;
    int lane = threadIdx.x & 31;
    if (wid >= EDGES_PER_LAYER) return;
    int b = wid >> 7, i = wid & 127;
    int base = l * EDGES_PER_LAYER + b * PE;
    int h = g_hkey[base + i];
    if (i > 0 && g_hkey[base + i - 1] == h) return;   // not segment start
    float s0 = 0.f, s1 = 0.f;
    int len = 0;
    while (i + len < PE && g_hkey[base + i + len] == h) {
        int e = g_hidx[base + i + len];
        const float* m = &g_msg[(b * PE + e) * PDEP];
        s0 += m[lane];
        s1 += m[lane + 32];
        len++;
    }
    float inv = 1.f / (float)len;
    float* c = &g_child[(b * PS + h) * PDEP];
    c[lane] = s0 * inv;
    c[lane + 32] = s1 * inv;
}

// ---------------------------------------------------------------------------
// Finish: out[:, :, 256:320] = final child
__global__ void k_finish(float* __restrict__ out) {
    const int64_t n = (int64_t)PB * PS * (PDEP / 4);
    int64_t stride = (int64_t)gridDim.x * blockDim.x;
    for (int64_t i = (int64_t)blockIdx.x * blockDim.x + threadIdx.x; i < n; i += stride) {
        int64_t row = i >> 4;     // / 16 float4 per row
        int64_t d4  = i & 15;
        *(float4*)&out[row * PF + PNODE + d4 * 4] = ((float4*)g_child)[i];
    }
}

// ---------------------------------------------------------------------------
extern "C" void kernel_launch(void* const* d_in, const int* in_sizes, int n_in,
                              void* d_out, int out_size) {
    const float* ctx   = (const float*)d_in[0];
    const float* W     = (const float*)d_in[1];
    const int*   heads = (const int*)d_in[2];
    const int*   tails = (const int*)d_in[3];
    const int*   rels  = (const int*)d_in[4];
    float*       out   = (float*)d_out;

    cudaFuncSetAttribute(k_msg, cudaFuncAttributeMaxDynamicSharedMemorySize, MSG_SMEM);

    k_init<<<2048, 256>>>(ctx, out);
    k_bucket_rel<<<PL, 256>>>(rels);
    {
        dim3 g(PL, PB);
        k_bucket_head<<<g, PE>>>(heads);
    }
    for (int l = 0; l < PL; l++) {
        dim3 gm(PR, 16);   // 16 chunks of 32 edges = capacity 512 edges per rel
        k_msg<<<gm, 128, MSG_SMEM>>>(ctx, W, tails, l);
        k_apply<<<512, 256>>>(l);
    }
    k_finish<<<2048, 256>>>(out);
}

// round 2
// speedup vs baseline: 1.4250x; 1.4250x over previous
#include <cuda_runtime.h>
#include <cstdint>

#define PB 32
#define PS 1024
#define PNODE 256
#define PDEP 64
#define PR 50
#define PL 16
#define PE 128
#define PF 320
#define NEDGE (PB * PE)   // 4096
#define LB 100            // persistent blocks (must be <= SM count for co-residency)

// ---------------- scratch (device globals; no allocation allowed) ----------
__device__ float g_child[PB * PS * PDEP];            // 8.4 MB
__device__ float g_msg[NEDGE * PDEP];                // 1 MB
__device__ float g_pmsg[PL * NEDGE * PDEP];          // 16.8 MB: ctx-part of msgs
__device__ int   g_rsort[PL * NEDGE];                // edge ids grouped by relation
__device__ int   g_rel_off[PL * (PR + 1)];
__device__ int   g_hkey[PL * NEDGE];                 // head-sorted keys per (l,b)
__device__ int   g_hidx[PL * NEDGE];
__device__ unsigned int g_bar;                       // grid barrier counter

// ---------------- f32x2 helpers -------------------------------------------
__device__ __forceinline__ void fma2(unsigned long long& acc,
                                     unsigned long long a, unsigned long long b) {
    asm("fma.rn.f32x2 %0, %1, %2, %0;" : "+l"(acc) : "l"(a), "l"(b));
}
__device__ __forceinline__ float hsum2(unsigned long long v) {
    unsigned int lo, hi;
    asm("mov.b64 {%0,%1}, %2;" : "=r"(lo), "=r"(hi) : "l"(v));
    return __uint_as_float(lo) + __uint_as_float(hi);
}

// ---------------- init: out[:,:,:256]=ctx, child=0, g_bar=0 ---------------
__global__ void k_init(const float* __restrict__ ctx, float* __restrict__ out) {
    if (blockIdx.x == 0 && threadIdx.x == 0) g_bar = 0;
    const int64_t n_ctx = (int64_t)PB * PS * (PNODE / 4);
    const int64_t n_chd = (int64_t)PB * PS * (PDEP / 4);
    const int64_t total = n_ctx + n_chd;
    int64_t stride = (int64_t)gridDim.x * blockDim.x;
    for (int64_t i = (int64_t)blockIdx.x * blockDim.x + threadIdx.x; i < total; i += stride) {
        if (i < n_ctx) {
            int64_t row = i >> 6, d4 = i & 63;
            float4 v = ((const float4*)ctx)[i];
            *(float4*)&out[row * PF + d4 * 4] = v;
        } else {
            ((float4*)g_child)[i - n_ctx] = make_float4(0.f, 0.f, 0.f, 0.f);
        }
    }
}

// ---------------- bucket edges by relation, per layer ----------------------
__global__ void k_bucket_rel(const int* __restrict__ rels) {
    int l = blockIdx.x;
    __shared__ int cnt[PR];
    __shared__ int off[PR];
    int tid = threadIdx.x;
    if (tid < PR) cnt[tid] = 0;
    __syncthreads();
    for (int idx = tid; idx < NEDGE; idx += blockDim.x) {
        int b = idx >> 7, e = idx & 127;
        atomicAdd(&cnt[rels[b * (PL * PE) + l * PE + e]], 1);
    }
    __syncthreads();
    if (tid == 0) {
        int s = 0;
        for (int r = 0; r < PR; r++) {
            off[r] = s;
            g_rel_off[l * (PR + 1) + r] = s;
            s += cnt[r];
        }
        g_rel_off[l * (PR + 1) + PR] = s;
    }
    __syncthreads();
    for (int idx = tid; idx < NEDGE; idx += blockDim.x) {
        int b = idx >> 7, e = idx & 127;
        int r = rels[b * (PL * PE) + l * PE + e];
        int pos = atomicAdd(&off[r], 1);
        g_rsort[l * NEDGE + pos] = idx;
    }
}

// ---------------- head rank-sort per (layer, batch) ------------------------
__global__ void k_bucket_head(const int* __restrict__ heads) {
    int l = blockIdx.x, b = blockIdx.y;
    int e = threadIdx.x;
    __shared__ int hs[PE];
    int h = heads[b * (PL * PE) + l * PE + e];
    hs[e] = h;
    __syncthreads();
    int rank = 0;
    #pragma unroll 8
    for (int o = 0; o < PE; o++) {
        int ho = hs[o];
        rank += (ho < h) || (ho == h && o < e);
    }
    int base = l * NEDGE + b * PE;
    g_hkey[base + rank] = h;
    g_hidx[base + rank] = e;
}

// ---------------- precompute ctx-part of all messages ----------------------
// block = (rel, layer, chunk64 x khalf). W1half [32][256] staged (stride 260),
// feats [64][256] staged (stride 260). Tile per thread: 4e x 2k, f32x2 along d.
#define PM_CHUNK 64
#define PM_STRIDE 260
#define PM_SMEM ((32 * PM_STRIDE + PM_CHUNK * PM_STRIDE) * (int)sizeof(float))

__global__ void __launch_bounds__(256, 2)
k_pmsg(const float* __restrict__ ctx, const float* __restrict__ W,
       const int* __restrict__ tails) {
    int r = blockIdx.x, l = blockIdx.y;
    int chunk = blockIdx.z >> 1, kh = blockIdx.z & 1;
    int off = g_rel_off[l * (PR + 1) + r];
    int end = g_rel_off[l * (PR + 1) + r + 1];
    int start = off + chunk * PM_CHUNK;
    if (start >= end) return;
    int ne = min(PM_CHUNK, end - start);

    extern __shared__ float sm[];
    float* Ws = sm;                        // [32][260]
    float* Fs = sm + 32 * PM_STRIDE;       // [64][260]
    __shared__ int eids[PM_CHUNK];
    int tid = threadIdx.x;

    // stage W half: rows k=0..31 (global kh*32+k), d=0..255, coalesced float4
    const float* Wg = W + ((int64_t)r * PDEP + kh * 32) * PF;
    #pragma unroll
    for (int t = 0; t < 8; t++) {
        int idx = tid + t * 256;           // 2048 float4
        int k = idx >> 6, c = idx & 63;
        *(float4*)&Ws[k * PM_STRIDE + c * 4] = *(const float4*)&Wg[k * PF + c * 4];
    }
    if (tid < PM_CHUNK)
        eids[tid] = (tid < ne) ? g_rsort[l * NEDGE + start + tid] : -1;
    __syncthreads();

    // gather feats (ctx rows of tails); zero-pad unused rows
    #pragma unroll
    for (int t = 0; t < 16; t++) {
        int idx = tid + t * 256;           // 4096 float4
        int j = idx >> 6, c = idx & 63;
        float4 v = make_float4(0.f, 0.f, 0.f, 0.f);
        int edge = eids[j];
        if (edge >= 0) {
            int b = edge >> 7, e = edge & 127;
            int tt = tails[b * (PL * PE) + l * PE + e];
            v = *(const float4*)&ctx[((int64_t)(b * PS + tt)) * PNODE + c * 4];
        }
        *(float4*)&Fs[j * PM_STRIDE + c * 4] = v;
    }
    __syncthreads();

    int eg = tid & 15;    // e in {eg, eg+16, eg+32, eg+48}
    int kg = tid >> 4;    // k in {kg, kg+16}
    unsigned long long acc[4][2];
    #pragma unroll
    for (int i = 0; i < 4; i++) { acc[i][0] = 0ull; acc[i][1] = 0ull; }

    #pragma unroll 4
    for (int d = 0; d < PNODE; d += 4) {
        ulonglong2 w0 = *(const ulonglong2*)&Ws[kg * PM_STRIDE + d];
        ulonglong2 w1 = *(const ulonglong2*)&Ws[(kg + 16) * PM_STRIDE + d];
        #pragma unroll
        for (int i = 0; i < 4; i++) {
            ulonglong2 f = *(const ulonglong2*)&Fs[(eg + 16 * i) * PM_STRIDE + d];
            fma2(acc[i][0], f.x, w0.x); fma2(acc[i][0], f.y, w0.y);
            fma2(acc[i][1], f.x, w1.x); fma2(acc[i][1], f.y, w1.y);
        }
    }

    #pragma unroll
    for (int i = 0; i < 4; i++) {
        int edge = eids[eg + 16 * i];
        if (edge >= 0) {
            float* dst = &g_pmsg[((int64_t)l * NEDGE + edge) * PDEP + kh * 32];
            dst[kg]      = hsum2(acc[i][0]);
            dst[kg + 16] = hsum2(acc[i][1]);
        }
    }
}

// ---------------- grid barrier for the persistent kernel -------------------
__device__ __forceinline__ void gsync(int* calls) {
    __syncthreads();
    (*calls)++;
    if (threadIdx.x == 0) {
        __threadfence();
        atomicAdd(&g_bar, 1);
        unsigned int target = (unsigned int)(LB * (*calls));
        while (*(volatile unsigned int*)&g_bar < target) { }
        __threadfence();
    }
    __syncthreads();
}

// ---------------- persistent per-layer kernel ------------------------------
// 100 blocks pinned to (rel, khalf). W2 half (32x64) staged ONCE for all 16
// layers. Phase 1: cmsg = W2 @ child[tail] + pmsg -> g_msg. Phase 2: apply.
// Cross-block data uses __ldcg/__stcg (L2-coherent).
__global__ void __launch_bounds__(256, 1)
k_layers(const float* __restrict__ W, const int* __restrict__ tails) {
    int bid = blockIdx.x;
    int r = bid >> 1, kh = bid & 1;
    __shared__ float Wc[32 * 68];
    __shared__ float Cs[32 * 68];
    __shared__ int eids[32];
    __shared__ int tls[32];
    int tid = threadIdx.x;
    int wid = tid >> 5, lane = tid & 31;

    // stage W2 half: k=0..31 (global kh*32+k), d=0..63 (cols 256..319 of W)
    const float* Wg = W + ((int64_t)r * PDEP + kh * 32) * PF + PNODE;
    #pragma unroll
    for (int t = 0; t < 2; t++) {
        int idx = tid + t * 256;           // 512 float4
        int k = idx >> 4, c = idx & 15;
        *(float4*)&Wc[k * 68 + c * 4] = *(const float4*)&Wg[k * PF + c * 4];
    }

    int calls = 0;
    for (int l = 0; l < PL; l++) {
        // ---- phase 1: child matvec + pmsg for this relation / k-half ----
        int off = g_rel_off[l * (PR + 1) + r];
        int end = g_rel_off[l * (PR + 1) + r + 1];
        for (int s = off; s < end; s += 32) {
            int ne = min(32, end - s);
            __syncthreads();               // protect Cs/eids reuse
            if (tid < 32) {
                int edge = (tid < ne) ? g_rsort[l * NEDGE + s + tid] : -1;
                eids[tid] = edge;
                int tv = 0;
                if (edge >= 0) {
                    int b = edge >> 7, e = edge & 127;
                    tv = b * PS + tails[b * (PL * PE) + l * PE + e];
                }
                tls[tid] = tv;
            }
            __syncthreads();
            #pragma unroll
            for (int t = 0; t < 2; t++) {
                int idx = tid + t * 256;   // 512 float4 = 32 rows x 16
                int j = idx >> 4, c = idx & 15;
                float4 v = make_float4(0.f, 0.f, 0.f, 0.f);
                if (eids[j] >= 0)
                    v = __ldcg((const float4*)&g_child[tls[j] * PDEP + c * 4]);
                *(float4*)&Cs[j * 68 + c * 4] = v;
            }
            __syncthreads();

            int eg = tid & 15, kg = tid >> 4;
            unsigned long long acc[2][2] = {0ull, 0ull, 0ull, 0ull};
            #pragma unroll
            for (int d = 0; d < PDEP; d += 4) {
                ulonglong2 w0 = *(const ulonglong2*)&Wc[kg * 68 + d];
                ulonglong2 w1 = *(const ulonglong2*)&Wc[(kg + 16) * 68 + d];
                ulonglong2 f0 = *(const ulonglong2*)&Cs[eg * 68 + d];
                ulonglong2 f1 = *(const ulonglong2*)&Cs[(eg + 16) * 68 + d];
                fma2(acc[0][0], f0.x, w0.x); fma2(acc[0][0], f0.y, w0.y);
                fma2(acc[0][1], f0.x, w1.x); fma2(acc[0][1], f0.y, w1.y);
                fma2(acc[1][0], f1.x, w0.x); fma2(acc[1][0], f1.y, w0.y);
                fma2(acc[1][1], f1.x, w1.x); fma2(acc[1][1], f1.y, w1.y);
            }
            #pragma unroll
            for (int i = 0; i < 2; i++) {
                int edge = eids[eg + 16 * i];
                if (edge >= 0) {
                    const float* pm = &g_pmsg[((int64_t)l * NEDGE + edge) * PDEP + kh * 32];
                    float* dst = &g_msg[edge * PDEP + kh * 32];
                    __stcg(&dst[kg],      hsum2(acc[i][0]) + pm[kg]);
                    __stcg(&dst[kg + 16], hsum2(acc[i][1]) + pm[kg + 16]);
                }
            }
        }
        gsync(&calls);

        // ---- phase 2: scatter-average onto heads (segment owners) ----
        for (int seg = bid * 8 + wid; seg < NEDGE; seg += LB * 8) {
            int b = seg >> 7, i = seg & 127;
            int base = l * NEDGE + b * PE;
            int h = g_hkey[base + i];
            if (i > 0 && g_hkey[base + i - 1] == h) continue;
            float s0 = 0.f, s1 = 0.f;
            int len = 0;
            while (i + len < PE && g_hkey[base + i + len] == h) {
                int e = g_hidx[base + i + len];
                const float* m = &g_msg[(b * PE + e) * PDEP];
                s0 += __ldcg(&m[lane]);
                s1 += __ldcg(&m[lane + 32]);
                len++;
            }
            float inv = 1.f / (float)len;
            float* c = &g_child[(b * PS + h) * PDEP];
            __stcg(&c[lane], s0 * inv);
            __stcg(&c[lane + 32], s1 * inv);
        }
        gsync(&calls);
    }
}

// ---------------- finish: out[:,:,256:320] = final child -------------------
__global__ void k_finish(float* __restrict__ out) {
    const int64_t n = (int64_t)PB * PS * (PDEP / 4);
    int64_t stride = (int64_t)gridDim.x * blockDim.x;
    for (int64_t i = (int64_t)blockIdx.x * blockDim.x + threadIdx.x; i < n; i += stride) {
        int64_t row = i >> 4, d4 = i & 15;
        *(float4*)&out[row * PF + PNODE + d4 * 4] = ((float4*)g_child)[i];
    }
}

// ---------------------------------------------------------------------------
extern "C" void kernel_launch(void* const* d_in, const int* in_sizes, int n_in,
                              void* d_out, int out_size) {
    const float* ctx   = (const float*)d_in[0];
    const float* W     = (const float*)d_in[1];
    const int*   heads = (const int*)d_in[2];
    const int*   tails = (const int*)d_in[3];
    const int*   rels  = (const int*)d_in[4];
    float*       out   = (float*)d_out;

    cudaFuncSetAttribute(k_pmsg, cudaFuncAttributeMaxDynamicSharedMemorySize, PM_SMEM);

    k_init<<<2048, 256>>>(ctx, out);
    k_bucket_rel<<<PL, 256>>>(rels);
    {
        dim3 g(PL, PB);
        k_bucket_head<<<g, PE>>>(heads);
    }
    {
        dim3 g(PR, PL, 6);   // 3 chunks of 64 edges (cap 192/rel) x 2 k-halves
        k_pmsg<<<g, 256, PM_SMEM>>>(ctx, W, tails);
    }
    k_layers<<<LB, 256>>>(W, tails);
    k_finish<<<2048, 256>>>(out);
}

// round 3
// speedup vs baseline: 1.9432x; 1.3636x over previous
#include <cuda_runtime.h>
#include <cstdint>

#define PB 32
#define PS 1024
#define PNODE 256
#define PDEP 64
#define PR 50
#define PL 16
#define PE 128
#define PF 320
#define NEDGE (PB * PE)     // 4096
#define NTOT (PL * NEDGE)   // 65536
#define LB 200              // persistent blocks (2/SM co-resident)

// ---------------- scratch (device globals) ---------------------------------
__device__ float g_child[PB * PS * PDEP];
__device__ float g_msg[NEDGE * PDEP];
__device__ float g_pmsg[PL * NEDGE * PDEP];          // ctx-part of msgs
__device__ int   g_rsort[NTOT];                      // per-layer rel-grouped edges
__device__ int   g_rel_off[PL * (PR + 1)];
__device__ int   g_gsort[NTOT];                      // global rel-grouped (l,edge)
__device__ int   g_gcnt[PR];
__device__ int   g_gbase[PR + 1];
__device__ int   g_gcur[PR];
__device__ int   g_hkey[NTOT];
__device__ int   g_hidx[NTOT];
__device__ unsigned int g_bar;

// ---------------- f32x2 helpers -------------------------------------------
__device__ __forceinline__ void fma2(unsigned long long& acc,
                                     unsigned long long a, unsigned long long b) {
    asm("fma.rn.f32x2 %0, %1, %2, %0;" : "+l"(acc) : "l"(a), "l"(b));
}
__device__ __forceinline__ float hsum2(unsigned long long v) {
    unsigned int lo, hi;
    asm("mov.b64 {%0,%1}, %2;" : "=r"(lo), "=r"(hi) : "l"(v));
    return __uint_as_float(lo) + __uint_as_float(hi);
}

// ---------------- init ------------------------------------------------------
__global__ void k_init(const float* __restrict__ ctx, float* __restrict__ out) {
    if (blockIdx.x == 0) {
        if (threadIdx.x == 0) g_bar = 0;
        if (threadIdx.x < PR) g_gcnt[threadIdx.x] = 0;
    }
    const int64_t n_ctx = (int64_t)PB * PS * (PNODE / 4);
    const int64_t n_chd = (int64_t)PB * PS * (PDEP / 4);
    const int64_t total = n_ctx + n_chd;
    int64_t stride = (int64_t)gridDim.x * blockDim.x;
    for (int64_t i = (int64_t)blockIdx.x * blockDim.x + threadIdx.x; i < total; i += stride) {
        if (i < n_ctx) {
            int64_t row = i >> 6, d4 = i & 63;
            float4 v = ((const float4*)ctx)[i];
            *(float4*)&out[row * PF + d4 * 4] = v;
        } else {
            ((float4*)g_child)[i - n_ctx] = make_float4(0.f, 0.f, 0.f, 0.f);
        }
    }
}

// ---------------- global rel bucketing (all layers) ------------------------
__global__ void k_gcount(const int* __restrict__ rels) {
    int stride = gridDim.x * blockDim.x;
    for (int i = blockIdx.x * blockDim.x + threadIdx.x; i < NTOT; i += stride)
        atomicAdd(&g_gcnt[rels[i]], 1);
}
__global__ void k_gprefix() {
    if (threadIdx.x == 0) {
        int s = 0;
        for (int r = 0; r < PR; r++) {
            g_gbase[r] = s;
            g_gcur[r] = s;
            s += g_gcnt[r];
        }
        g_gbase[PR] = s;
    }
}
__global__ void k_gscatter(const int* __restrict__ rels) {
    int stride = gridDim.x * blockDim.x;
    for (int i = blockIdx.x * blockDim.x + threadIdx.x; i < NTOT; i += stride) {
        int r = rels[i];
        int b = i >> 11, l = (i >> 7) & 15, e = i & 127;
        int pos = atomicAdd(&g_gcur[r], 1);
        g_gsort[pos] = (l << 12) | (b << 7) | e;
    }
}

// ---------------- per-layer rel bucketing (for chain) ----------------------
__global__ void k_bucket_rel(const int* __restrict__ rels) {
    int l = blockIdx.x;
    __shared__ int cnt[PR];
    __shared__ int off[PR];
    int tid = threadIdx.x;
    if (tid < PR) cnt[tid] = 0;
    __syncthreads();
    for (int idx = tid; idx < NEDGE; idx += blockDim.x) {
        int b = idx >> 7, e = idx & 127;
        atomicAdd(&cnt[rels[b * (PL * PE) + l * PE + e]], 1);
    }
    __syncthreads();
    if (tid == 0) {
        int s = 0;
        for (int r = 0; r < PR; r++) {
            off[r] = s;
            g_rel_off[l * (PR + 1) + r] = s;
            s += cnt[r];
        }
        g_rel_off[l * (PR + 1) + PR] = s;
    }
    __syncthreads();
    for (int idx = tid; idx < NEDGE; idx += blockDim.x) {
        int b = idx >> 7, e = idx & 127;
        int r = rels[b * (PL * PE) + l * PE + e];
        int pos = atomicAdd(&off[r], 1);
        g_rsort[l * NEDGE + pos] = idx;
    }
}

// ---------------- head rank-sort per (layer, batch) ------------------------
__global__ void k_bucket_head(const int* __restrict__ heads) {
    int l = blockIdx.x, b = blockIdx.y;
    int e = threadIdx.x;
    __shared__ int hs[PE];
    int h = heads[b * (PL * PE) + l * PE + e];
    hs[e] = h;
    __syncthreads();
    int rank = 0;
    #pragma unroll 8
    for (int o = 0; o < PE; o++) {
        int ho = hs[o];
        rank += (ho < h) || (ho == h && o < e);
    }
    int base = l * NEDGE + b * PE;
    g_hkey[base + rank] = h;
    g_hidx[base + rank] = e;
}

// ---------------- pmsg: ctx-part of all messages, full-k blocks ------------
// block = (rel, chunk128). W[r] full 64x256 staged (stride 260), F 128x256
// staged (stride 260). Per-thread 4e x 8k register tile, f32x2 along d.
#define PM_STRIDE 260
#define PM_SMEM ((64 * PM_STRIDE + 128 * PM_STRIDE) * (int)sizeof(float))

__global__ void __launch_bounds__(256, 1)
k_pmsg(const float* __restrict__ ctx, const float* __restrict__ W,
       const int* __restrict__ tails) {
    int r = blockIdx.x, chunk = blockIdx.y;
    int base = g_gbase[r], end = g_gbase[r + 1];
    int start = base + chunk * 128;
    if (start >= end) return;
    int ne = min(128, end - start);

    extern __shared__ float sm[];
    float* Ws = sm;                        // [64][260]
    float* Fs = sm + 64 * PM_STRIDE;       // [128][260]
    __shared__ int seid[128];
    __shared__ int stail[128];
    int tid = threadIdx.x;

    if (tid < 128) {
        int v = (tid < ne) ? g_gsort[start + tid] : -1;
        seid[tid] = v;
        int tnode = 0;
        if (v >= 0) {
            int b = (v >> 7) & 31, l = v >> 12, e = v & 127;
            tnode = b * PS + tails[b * (PL * PE) + l * PE + e];
        }
        stail[tid] = tnode;
    }
    // stage W[r]: 64 rows x 256 cols, coalesced float4
    const float* Wg = W + (int64_t)r * PDEP * PF;
    #pragma unroll
    for (int t = 0; t < 16; t++) {
        int idx = tid + t * 256;           // 4096 float4
        int k = idx >> 6, c = idx & 63;
        *(float4*)&Ws[k * PM_STRIDE + c * 4] = *(const float4*)&Wg[k * PF + c * 4];
    }
    __syncthreads();

    // gather ctx rows of tails
    #pragma unroll
    for (int t = 0; t < 32; t++) {
        int idx = tid + t * 256;           // 8192 float4
        int row = idx >> 6, c = idx & 63;
        float4 v = make_float4(0.f, 0.f, 0.f, 0.f);
        if (seid[row] >= 0)
            v = *(const float4*)&ctx[(int64_t)stail[row] * PNODE + c * 4];
        *(float4*)&Fs[row * PM_STRIDE + c * 4] = v;
    }
    __syncthreads();

    int eg = tid & 31;    // e in {eg, +32, +64, +96}
    int kg = tid >> 5;    // k in {kg, +8, ..., +56}
    unsigned long long acc[4][8];
    #pragma unroll
    for (int i = 0; i < 4; i++)
        #pragma unroll
        for (int j = 0; j < 8; j++) acc[i][j] = 0ull;

    #pragma unroll 4
    for (int d = 0; d < PNODE; d += 4) {
        ulonglong2 w[8];
        #pragma unroll
        for (int j = 0; j < 8; j++)
            w[j] = *(const ulonglong2*)&Ws[(kg + 8 * j) * PM_STRIDE + d];
        #pragma unroll
        for (int i = 0; i < 4; i++) {
            ulonglong2 f = *(const ulonglong2*)&Fs[(eg + 32 * i) * PM_STRIDE + d];
            #pragma unroll
            for (int j = 0; j < 8; j++) {
                fma2(acc[i][j], f.x, w[j].x);
                fma2(acc[i][j], f.y, w[j].y);
            }
        }
    }

    #pragma unroll
    for (int i = 0; i < 4; i++) {
        int v = seid[eg + 32 * i];
        if (v >= 0) {
            int l = v >> 12, edge = v & 4095;
            float* dst = &g_pmsg[((int64_t)l * NEDGE + edge) * PDEP];
            #pragma unroll
            for (int j = 0; j < 8; j++)
                dst[kg + 8 * j] = hsum2(acc[i][j]);
        }
    }
}

// ---------------- grid barrier --------------------------------------------
__device__ __forceinline__ void gsync(int* calls) {
    __syncthreads();
    (*calls)++;
    if (threadIdx.x == 0) {
        __threadfence();
        atomicAdd(&g_bar, 1);
        unsigned int target = (unsigned int)(LB * (*calls));
        while (*(volatile unsigned int*)&g_bar < target) { }
        __threadfence();
    }
    __syncthreads();
}

// ---------------- persistent chain kernel ----------------------------------
// 200 blocks: (rel, khalf, edge-half). W2 half staged once for all layers.
// Phase1: single 64-edge tile per layer (prefetched ids). Phase2: blocks
// 0..127 (4 per batch) with smem-staged hkey/hidx.
__global__ void __launch_bounds__(256, 2)
k_layers(const float* __restrict__ W, const int* __restrict__ tails) {
    int bid = blockIdx.x;
    int r = bid >> 2, kh = (bid >> 1) & 1, h = bid & 1;
    __shared__ float Wc[32 * 68];
    __shared__ float Cs[64 * 68];
    __shared__ int seids[64];
    __shared__ int stls[64];
    __shared__ int shk[128];
    __shared__ int shx[128];
    int tid = threadIdx.x;
    int wid = tid >> 5, lane = tid & 31;

    // stage W2 half (k rows kh*32.., cols 256..319)
    {
        const float* Wg = W + ((int64_t)r * PDEP + kh * 32) * PF + PNODE;
        #pragma unroll
        for (int t = 0; t < 2; t++) {
            int idx = tid + t * 256;       // 512 float4
            int k = idx >> 4, c = idx & 15;
            *(float4*)&Wc[k * 68 + c * 4] = *(const float4*)&Wg[k * PF + c * 4];
        }
    }

    // prefetch layer 0 edge ids + tails (registers)
    int pe = -1, pt = 0;
    if (tid < 64) {
        int off0 = g_rel_off[r];
        int cnt0 = g_rel_off[r + 1] - off0;
        int j = 2 * tid + h;
        if (j < cnt0) {
            pe = g_rsort[off0 + j];
            int b = pe >> 7, e = pe & 127;
            pt = b * PS + tails[b * (PL * PE) + e];
        }
    }

    int calls = 0;
    for (int l = 0; l < PL; l++) {
        int off = g_rel_off[l * (PR + 1) + r];
        int cnt = g_rel_off[l * (PR + 1) + r + 1] - off;
        int nh = (cnt > h) ? ((cnt - h + 1) >> 1) : 0;

        for (int tb = 0; tb < nh; tb += 64) {
            __syncthreads();
            if (tid < 64) {
                int e_ = -1, t_ = 0;
                if (tb == 0) { e_ = pe; t_ = pt; }
                else {
                    int i = tb + tid;
                    if (i < nh) {
                        int j = 2 * i + h;
                        e_ = g_rsort[l * NEDGE + off + j];
                        int b = e_ >> 7, e = e_ & 127;
                        t_ = b * PS + tails[b * (PL * PE) + l * PE + e];
                    }
                }
                seids[tid] = e_;
                stls[tid] = t_;
            }
            __syncthreads();
            // gather child rows (one MLP burst)
            #pragma unroll
            for (int t = 0; t < 4; t++) {
                int idx = tid + t * 256;   // 1024 float4 = 64 rows x 16
                int row = idx >> 4, c = idx & 15;
                float4 v = make_float4(0.f, 0.f, 0.f, 0.f);
                if (seids[row] >= 0)
                    v = __ldcg((const float4*)&g_child[stls[row] * PDEP + c * 4]);
                *(float4*)&Cs[row * 68 + c * 4] = v;
            }
            __syncthreads();

            int eg = tid & 15, kg = tid >> 4;
            // pmsg prefetch (independent loads)
            float pm[4][2];
            #pragma unroll
            for (int i = 0; i < 4; i++) {
                int edge = seids[eg + 16 * i];
                pm[i][0] = 0.f; pm[i][1] = 0.f;
                if (edge >= 0) {
                    const float* p = &g_pmsg[((int64_t)l * NEDGE + edge) * PDEP + kh * 32];
                    pm[i][0] = __ldcg(&p[kg]);
                    pm[i][1] = __ldcg(&p[kg + 16]);
                }
            }
            unsigned long long acc[4][2];
            #pragma unroll
            for (int i = 0; i < 4; i++) { acc[i][0] = 0ull; acc[i][1] = 0ull; }
            #pragma unroll
            for (int d = 0; d < PDEP; d += 4) {
                ulonglong2 w0 = *(const ulonglong2*)&Wc[kg * 68 + d];
                ulonglong2 w1 = *(const ulonglong2*)&Wc[(kg + 16) * 68 + d];
                #pragma unroll
                for (int i = 0; i < 4; i++) {
                    ulonglong2 f = *(const ulonglong2*)&Cs[(eg + 16 * i) * 68 + d];
                    fma2(acc[i][0], f.x, w0.x); fma2(acc[i][0], f.y, w0.y);
                    fma2(acc[i][1], f.x, w1.x); fma2(acc[i][1], f.y, w1.y);
                }
            }
            #pragma unroll
            for (int i = 0; i < 4; i++) {
                int edge = seids[eg + 16 * i];
                if (edge >= 0) {
                    float* dst = &g_msg[edge * PDEP + kh * 32];
                    __stcg(&dst[kg],      hsum2(acc[i][0]) + pm[i][0]);
                    __stcg(&dst[kg + 16], hsum2(acc[i][1]) + pm[i][1]);
                }
            }
        }

        // prefetch next layer's tile-0 ids/tails (hidden behind barrier+phase2)
        pe = -1; pt = 0;
        if (l + 1 < PL && tid < 64) {
            int offn = g_rel_off[(l + 1) * (PR + 1) + r];
            int cntn = g_rel_off[(l + 1) * (PR + 1) + r + 1] - offn;
            int j = 2 * tid + h;
            if (j < cntn) {
                pe = g_rsort[(l + 1) * NEDGE + offn + j];
                int b = pe >> 7, e = pe & 127;
                pt = b * PS + tails[b * (PL * PE) + (l + 1) * PE + e];
            }
        }
        gsync(&calls);

        // ---- phase 2: scatter-average (blocks 0..127, 4 per batch) ----
        if (bid < 128) {
            int b = bid >> 2, q = bid & 3;
            if (tid < 128) {
                shk[tid] = g_hkey[l * NEDGE + b * PE + tid];
                shx[tid] = g_hidx[l * NEDGE + b * PE + tid];
            }
            __syncthreads();
            for (int p = q * 32 + wid; p < q * 32 + 32; p += 8) {
                int hseg = shk[p];
                if (p > 0 && shk[p - 1] == hseg) continue;
                int len = 1;
                while (p + len < PE && shk[p + len] == hseg) len++;
                float s0 = 0.f, s1 = 0.f;
                for (int j = 0; j < len; j++) {
                    int e = shx[p + j];
                    const float* m = &g_msg[(b * PE + e) * PDEP];
                    s0 += __ldcg(&m[lane]);
                    s1 += __ldcg(&m[lane + 32]);
                }
                float inv = 1.f / (float)len;
                float* c = &g_child[(b * PS + hseg) * PDEP];
                __stcg(&c[lane], s0 * inv);
                __stcg(&c[lane + 32], s1 * inv);
            }
        }
        gsync(&calls);
    }
}

// ---------------- finish ----------------------------------------------------
__global__ void k_finish(float* __restrict__ out) {
    const int64_t n = (int64_t)PB * PS * (PDEP / 4);
    int64_t stride = (int64_t)gridDim.x * blockDim.x;
    for (int64_t i = (int64_t)blockIdx.x * blockDim.x + threadIdx.x; i < n; i += stride) {
        int64_t row = i >> 4, d4 = i & 15;
        *(float4*)&out[row * PF + PNODE + d4 * 4] = ((float4*)g_child)[i];
    }
}

// ---------------------------------------------------------------------------
extern "C" void kernel_launch(void* const* d_in, const int* in_sizes, int n_in,
                              void* d_out, int out_size) {
    const float* ctx   = (const float*)d_in[0];
    const float* W     = (const float*)d_in[1];
    const int*   heads = (const int*)d_in[2];
    const int*   tails = (const int*)d_in[3];
    const int*   rels  = (const int*)d_in[4];
    float*       out   = (float*)d_out;

    cudaFuncSetAttribute(k_pmsg, cudaFuncAttributeMaxDynamicSharedMemorySize, PM_SMEM);

    k_init<<<2048, 256>>>(ctx, out);
    k_gcount<<<64, 256>>>(rels);
    k_gprefix<<<1, 32>>>();
    k_gscatter<<<64, 256>>>(rels);
    k_bucket_rel<<<PL, 256>>>(rels);
    {
        dim3 g(PL, PB);
        k_bucket_head<<<g, PE>>>(heads);
    }
    {
        dim3 g(PR, 12);   // chunks of 128 edges; capacity 1536/rel (mean 1310)
        k_pmsg<<<g, 256, PM_SMEM>>>(ctx, W, tails);
    }
    k_layers<<<LB, 256>>>(W, tails);
    k_finish<<<2048, 256>>>(out);
}

// round 4
// speedup vs baseline: 2.0317x; 1.0456x over previous
#include <cuda_runtime.h>
#include <cstdint>

#define PB 32
#define PS 1024
#define PNODE 256
#define PDEP 64
#define PR 50
#define PL 16
#define PE 128
#define PF 320
#define NEDGE (PB * PE)     // 4096
#define NTOT (PL * NEDGE)   // 65536
#define NGRP 4              // independent batch groups
#define GB (PB / NGRP)      // 8 batches per group
#define RB PR               // blocks per group (one per relation)
#define LBT (NGRP * RB)     // 200 chain blocks
#define MAXCHUNK 640

// ---------------- scratch (device globals) ---------------------------------
__device__ float g_child[PB * PS * PDEP];
__device__ float g_msg[NEDGE * PDEP];
__device__ float g_pmsg[PL * NEDGE * PDEP];
__device__ int   g_gsort[NTOT];                  // global rel-grouped (l,b,e)
__device__ int   g_gcnt[PR];
__device__ int   g_gbase[PR + 1];
__device__ int   g_gcur[PR];
__device__ int   g_chunk_rel[MAXCHUNK];
__device__ int   g_chunk_start[MAXCHUNK];
__device__ int   g_chunk_ne[MAXCHUNK];
__device__ int   g_nchunks;
__device__ unsigned int g_ticket;
__device__ int   g_rsortg[NGRP * PL * 1024];     // per (group,layer) rel-grouped
__device__ int   g_rel_offg[NGRP * PL * (PR + 1)];
__device__ int   g_hkey[NTOT];
__device__ int   g_hidx[NTOT];
__device__ unsigned int g_bar4[NGRP];

// ---------------- f32x2 helpers -------------------------------------------
__device__ __forceinline__ void fma2(unsigned long long& acc,
                                     unsigned long long a, unsigned long long b) {
    asm("fma.rn.f32x2 %0, %1, %2, %0;" : "+l"(acc) : "l"(a), "l"(b));
}
__device__ __forceinline__ float hsum2(unsigned long long v) {
    unsigned int lo, hi;
    asm("mov.b64 {%0,%1}, %2;" : "=r"(lo), "=r"(hi) : "l"(v));
    return __uint_as_float(lo) + __uint_as_float(hi);
}

// ---------------- init ------------------------------------------------------
__global__ void k_init(const float* __restrict__ ctx, float* __restrict__ out) {
    if (blockIdx.x == 0) {
        if (threadIdx.x == 0) g_ticket = 0;
        if (threadIdx.x < NGRP) g_bar4[threadIdx.x] = 0;
        if (threadIdx.x < PR) g_gcnt[threadIdx.x] = 0;
    }
    const int64_t n_ctx = (int64_t)PB * PS * (PNODE / 4);
    const int64_t n_chd = (int64_t)PB * PS * (PDEP / 4);
    const int64_t total = n_ctx + n_chd;
    int64_t stride = (int64_t)gridDim.x * blockDim.x;
    for (int64_t i = (int64_t)blockIdx.x * blockDim.x + threadIdx.x; i < total; i += stride) {
        if (i < n_ctx) {
            int64_t row = i >> 6, d4 = i & 63;
            float4 v = ((const float4*)ctx)[i];
            *(float4*)&out[row * PF + d4 * 4] = v;
        } else {
            ((float4*)g_child)[i - n_ctx] = make_float4(0.f, 0.f, 0.f, 0.f);
        }
    }
}

// ---------------- global rel histogram (smem-local, low contention) --------
__global__ void k_gcount(const int* __restrict__ rels) {
    __shared__ int cnt[PR];
    int tid = threadIdx.x;
    if (tid < PR) cnt[tid] = 0;
    __syncthreads();
    int base = blockIdx.x * 1024;
    #pragma unroll
    for (int t = 0; t < 4; t++)
        atomicAdd(&cnt[rels[base + tid + t * 256]], 1);
    __syncthreads();
    if (tid < PR && cnt[tid] > 0) atomicAdd(&g_gcnt[tid], cnt[tid]);
}

// prefix + chunk worklist (single thread; trivial sizes)
__global__ void k_gprefix() {
    if (threadIdx.x == 0) {
        int s = 0, nc = 0;
        for (int r = 0; r < PR; r++) {
            g_gbase[r] = s;
            g_gcur[r] = s;
            int c = g_gcnt[r];
            for (int off = 0; off < c; off += 128) {
                g_chunk_rel[nc] = r;
                g_chunk_start[nc] = s + off;
                g_chunk_ne[nc] = min(128, c - off);
                nc++;
            }
            s += c;
        }
        g_gbase[PR] = s;
        g_nchunks = nc;
    }
}

// scatter with per-block range reservation (one atomic per (block,rel))
__global__ void k_gscatter(const int* __restrict__ rels) {
    __shared__ int cnt[PR], base[PR], cur[PR];
    int tid = threadIdx.x;
    if (tid < PR) { cnt[tid] = 0; cur[tid] = 0; }
    __syncthreads();
    int bstart = blockIdx.x * 1024;
    #pragma unroll
    for (int t = 0; t < 4; t++)
        atomicAdd(&cnt[rels[bstart + tid + t * 256]], 1);
    __syncthreads();
    if (tid < PR) base[tid] = atomicAdd(&g_gcur[tid], cnt[tid]);
    __syncthreads();
    #pragma unroll
    for (int t = 0; t < 4; t++) {
        int idx = bstart + tid + t * 256;
        int r = rels[idx];
        int pos = base[r] + atomicAdd(&cur[r], 1);
        int b = idx >> 11, l = (idx >> 7) & 15, e = idx & 127;
        g_gsort[pos] = (l << 12) | (b << 7) | e;
    }
}

// ---------------- per (group,layer) rel bucketing --------------------------
__global__ void k_bucket_relg(const int* __restrict__ rels) {
    int g = blockIdx.x >> 4, l = blockIdx.x & 15;
    __shared__ int cnt[PR], cur[PR];
    int tid = threadIdx.x;
    if (tid < PR) cnt[tid] = 0;
    __syncthreads();
    #pragma unroll
    for (int t = 0; t < 4; t++) {
        int i = tid + t * 256;           // 0..1023
        int b = g * GB + (i >> 7), e = i & 127;
        atomicAdd(&cnt[rels[b * (PL * PE) + l * PE + e]], 1);
    }
    __syncthreads();
    if (tid == 0) {
        int s = 0;
        int ob = (g * PL + l) * (PR + 1);
        for (int r = 0; r < PR; r++) {
            g_rel_offg[ob + r] = s;
            cur[r] = s;
            s += cnt[r];
        }
        g_rel_offg[ob + PR] = s;
    }
    __syncthreads();
    #pragma unroll
    for (int t = 0; t < 4; t++) {
        int i = tid + t * 256;
        int b = g * GB + (i >> 7), e = i & 127;
        int r = rels[b * (PL * PE) + l * PE + e];
        int pos = atomicAdd(&cur[r], 1);
        g_rsortg[(g * PL + l) * 1024 + pos] = (b << 7) | e;
    }
}

// ---------------- head rank-sort per (layer, batch) ------------------------
__global__ void k_bucket_head(const int* __restrict__ heads) {
    int l = blockIdx.x, b = blockIdx.y;
    int e = threadIdx.x;
    __shared__ int hs[PE];
    int h = heads[b * (PL * PE) + l * PE + e];
    hs[e] = h;
    __syncthreads();
    int rank = 0;
    #pragma unroll 8
    for (int o = 0; o < PE; o++) {
        int ho = hs[o];
        rank += (ho < h) || (ho == h && o < e);
    }
    int base = l * NEDGE + b * PE;
    g_hkey[base + rank] = h;
    g_hidx[base + rank] = e;
}

// ---------------- pmsg: persistent ticket-queue GEMM-ish kernel ------------
#define PM_STRIDE 260
#define PM_SMEM ((64 * PM_STRIDE + 128 * PM_STRIDE) * (int)sizeof(float))

__global__ void __launch_bounds__(256, 1)
k_pmsg(const float* __restrict__ ctx, const float* __restrict__ W,
       const int* __restrict__ tails) {
    extern __shared__ float sm[];
    float* Ws = sm;                        // [64][260]
    float* Fs = sm + 64 * PM_STRIDE;       // [128][260]
    __shared__ int seid[128];
    __shared__ int stail[128];
    __shared__ int s_chunk;
    int tid = threadIdx.x;

    while (true) {
        if (tid == 0) s_chunk = atomicAdd(&g_ticket, 1);
        __syncthreads();
        int c = s_chunk;
        if (c >= g_nchunks) break;
        int r = g_chunk_rel[c];
        int start = g_chunk_start[c];
        int ne = g_chunk_ne[c];

        if (tid < 128) {
            int v = (tid < ne) ? g_gsort[start + tid] : -1;
            seid[tid] = v;
            int tnode = 0;
            if (v >= 0) {
                int b = (v >> 7) & 31, l = v >> 12, e = v & 127;
                tnode = b * PS + tails[b * (PL * PE) + l * PE + e];
            }
            stail[tid] = tnode;
        }
        const float* Wg = W + (int64_t)r * PDEP * PF;
        #pragma unroll
        for (int t = 0; t < 16; t++) {
            int idx = tid + t * 256;       // 4096 float4
            int k = idx >> 6, cc = idx & 63;
            *(float4*)&Ws[k * PM_STRIDE + cc * 4] = *(const float4*)&Wg[k * PF + cc * 4];
        }
        __syncthreads();

        #pragma unroll
        for (int t = 0; t < 32; t++) {
            int idx = tid + t * 256;       // 8192 float4
            int row = idx >> 6, cc = idx & 63;
            float4 v = make_float4(0.f, 0.f, 0.f, 0.f);
            if (seid[row] >= 0)
                v = *(const float4*)&ctx[(int64_t)stail[row] * PNODE + cc * 4];
            *(float4*)&Fs[row * PM_STRIDE + cc * 4] = v;
        }
        __syncthreads();

        int eg = tid & 31;    // e in {eg, +32, +64, +96}
        int kg = tid >> 5;    // k in {kg, +8, ..., +56}
        unsigned long long acc[4][8];
        #pragma unroll
        for (int i = 0; i < 4; i++)
            #pragma unroll
            for (int j = 0; j < 8; j++) acc[i][j] = 0ull;

        #pragma unroll 4
        for (int d = 0; d < PNODE; d += 4) {
            ulonglong2 w[8];
            #pragma unroll
            for (int j = 0; j < 8; j++)
                w[j] = *(const ulonglong2*)&Ws[(kg + 8 * j) * PM_STRIDE + d];
            #pragma unroll
            for (int i = 0; i < 4; i++) {
                ulonglong2 f = *(const ulonglong2*)&Fs[(eg + 32 * i) * PM_STRIDE + d];
                #pragma unroll
                for (int j = 0; j < 8; j++) {
                    fma2(acc[i][j], f.x, w[j].x);
                    fma2(acc[i][j], f.y, w[j].y);
                }
            }
        }

        #pragma unroll
        for (int i = 0; i < 4; i++) {
            int v = seid[eg + 32 * i];
            if (v >= 0) {
                int l = v >> 12, edge = v & 4095;
                float* dst = &g_pmsg[((int64_t)l * NEDGE + edge) * PDEP];
                #pragma unroll
                for (int j = 0; j < 8; j++)
                    dst[kg + 8 * j] = hsum2(acc[i][j]);
            }
        }
        __syncthreads();
    }
}

// ---------------- group-local grid barrier ---------------------------------
__device__ __forceinline__ void gsync_g(int g, int* calls) {
    __syncthreads();
    (*calls)++;
    if (threadIdx.x == 0) {
        __threadfence();
        atomicAdd(&g_bar4[g], 1);
        unsigned int target = (unsigned int)(RB * (*calls));
        while (*(volatile unsigned int*)&g_bar4[g] < target) { }
        __threadfence();
    }
    __syncthreads();
}

// ---------------- persistent chain: 4 independent groups x 50 rel blocks ---
__global__ void __launch_bounds__(256, 2)
k_layers(const float* __restrict__ W, const int* __restrict__ tails,
         float* __restrict__ out) {
    int bid = blockIdx.x;
    int g = bid / RB, r = bid - g * RB;
    __shared__ float Wc[64 * 68];
    __shared__ float Cs[64 * 68];
    __shared__ int seids[64];
    __shared__ int stls[64];
    __shared__ int shk[128];
    __shared__ int shx[128];
    int tid = threadIdx.x;
    int wid = tid >> 5, lane = tid & 31;

    // stage full W2[r] (64 x 64, cols 256..319) once for all layers
    {
        const float* Wg = W + (int64_t)r * PDEP * PF + PNODE;
        #pragma unroll
        for (int t = 0; t < 4; t++) {
            int idx = tid + t * 256;       // 1024 float4
            int k = idx >> 4, c = idx & 15;
            *(float4*)&Wc[k * 68 + c * 4] = *(const float4*)&Wg[k * PF + c * 4];
        }
    }

    int calls = 0;
    for (int l = 0; l < PL; l++) {
        // ---- phase 1: msg = W2 @ child[tail] + pmsg, this group's edges ----
        int ob = (g * PL + l) * (PR + 1);
        int off = g_rel_offg[ob + r];
        int end = g_rel_offg[ob + r + 1];
        for (int s = off; s < end; s += 64) {
            int ne = min(64, end - s);
            __syncthreads();
            if (tid < 64) {
                int v = -1, tn = 0;
                if (tid < ne) {
                    v = g_rsortg[(g * PL + l) * 1024 + s + tid];
                    int b = v >> 7, e = v & 127;
                    tn = b * PS + tails[b * (PL * PE) + l * PE + e];
                }
                seids[tid] = v;
                stls[tid] = tn;
            }
            __syncthreads();
            if (l > 0) {
                #pragma unroll
                for (int t = 0; t < 4; t++) {
                    int idx = tid + t * 256;   // 1024 float4 = 64 rows x 16
                    int row = idx >> 4, c = idx & 15;
                    float4 v = make_float4(0.f, 0.f, 0.f, 0.f);
                    if (seids[row] >= 0)
                        v = __ldcg((const float4*)&g_child[stls[row] * PDEP + c * 4]);
                    *(float4*)&Cs[row * 68 + c * 4] = v;
                }
                __syncthreads();
            }

            int eg = tid & 15, kg = tid >> 4;
            float pm[4][4];
            #pragma unroll
            for (int i = 0; i < 4; i++) {
                int edge = seids[eg + 16 * i];
                #pragma unroll
                for (int j = 0; j < 4; j++) pm[i][j] = 0.f;
                if (edge >= 0) {
                    const float* p = &g_pmsg[((int64_t)l * NEDGE + edge) * PDEP];
                    #pragma unroll
                    for (int j = 0; j < 4; j++)
                        pm[i][j] = __ldcg(&p[kg + 16 * j]);
                }
            }
            unsigned long long acc[4][4];
            #pragma unroll
            for (int i = 0; i < 4; i++)
                #pragma unroll
                for (int j = 0; j < 4; j++) acc[i][j] = 0ull;
            if (l > 0) {
                #pragma unroll
                for (int d = 0; d < PDEP; d += 4) {
                    ulonglong2 w[4];
                    #pragma unroll
                    for (int j = 0; j < 4; j++)
                        w[j] = *(const ulonglong2*)&Wc[(kg + 16 * j) * 68 + d];
                    #pragma unroll
                    for (int i = 0; i < 4; i++) {
                        ulonglong2 f = *(const ulonglong2*)&Cs[(eg + 16 * i) * 68 + d];
                        #pragma unroll
                        for (int j = 0; j < 4; j++) {
                            fma2(acc[i][j], f.x, w[j].x);
                            fma2(acc[i][j], f.y, w[j].y);
                        }
                    }
                }
            }
            #pragma unroll
            for (int i = 0; i < 4; i++) {
                int edge = seids[eg + 16 * i];
                if (edge >= 0) {
                    float* dst = &g_msg[edge * PDEP];
                    #pragma unroll
                    for (int j = 0; j < 4; j++)
                        __stcg(&dst[kg + 16 * j], hsum2(acc[i][j]) + pm[i][j]);
                }
            }
        }
        gsync_g(g, &calls);

        // ---- phase 2: scatter-average (32 of 50 blocks: 8 batches x 4) ----
        if (r < 32) {
            int b = g * GB + (r >> 2), q = r & 3;
            if (tid < 128) {
                shk[tid] = g_hkey[l * NEDGE + b * PE + tid];
                shx[tid] = g_hidx[l * NEDGE + b * PE + tid];
            }
            __syncthreads();
            for (int p = q * 32 + wid; p < q * 32 + 32; p += 8) {
                int hseg = shk[p];
                if (p > 0 && shk[p - 1] == hseg) continue;
                int len = 1;
                while (p + len < PE && shk[p + len] == hseg) len++;
                float s0 = 0.f, s1 = 0.f;
                for (int j = 0; j < len; j++) {
                    int e = shx[p + j];
                    const float* m = &g_msg[(b * PE + e) * PDEP];
                    s0 += __ldcg(&m[lane]);
                    s1 += __ldcg(&m[lane + 32]);
                }
                float inv = 1.f / (float)len;
                float* c = &g_child[(b * PS + hseg) * PDEP];
                __stcg(&c[lane], s0 * inv);
                __stcg(&c[lane + 32], s1 * inv);
            }
        }
        gsync_g(g, &calls);
    }

    // ---- out[:, :, 256:320] for this group's 8 batches (no global barrier) --
    for (int idx = r * 256 + tid; idx < GB * PS * 16; idx += RB * 256) {
        int row = idx >> 4, c = idx & 15;
        int b = g * GB + (row >> 10), s = row & 1023;
        float4 v;
        v.x = __ldcg(&g_child[(b * PS + s) * PDEP + c * 4 + 0]);
        v.y = __ldcg(&g_child[(b * PS + s) * PDEP + c * 4 + 1]);
        v.z = __ldcg(&g_child[(b * PS + s) * PDEP + c * 4 + 2]);
        v.w = __ldcg(&g_child[(b * PS + s) * PDEP + c * 4 + 3]);
        *(float4*)&out[((int64_t)(b * PS + s)) * PF + PNODE + c * 4] = v;
    }
}

// ---------------------------------------------------------------------------
extern "C" void kernel_launch(void* const* d_in, const int* in_sizes, int n_in,
                              void* d_out, int out_size) {
    const float* ctx   = (const float*)d_in[0];
    const float* W     = (const float*)d_in[1];
    const int*   heads = (const int*)d_in[2];
    const int*   tails = (const int*)d_in[3];
    const int*   rels  = (const int*)d_in[4];
    float*       out   = (float*)d_out;

    cudaFuncSetAttribute(k_pmsg, cudaFuncAttributeMaxDynamicSharedMemorySize, PM_SMEM);

    k_init<<<2048, 256>>>(ctx, out);
    k_gcount<<<64, 256>>>(rels);
    k_gprefix<<<1, 32>>>();
    k_gscatter<<<64, 256>>>(rels);
    k_bucket_relg<<<NGRP * PL, 256>>>(rels);
    {
        dim3 g(PL, PB);
        k_bucket_head<<<g, PE>>>(heads);
    }
    k_pmsg<<<148, 256, PM_SMEM>>>(ctx, W, tails);
    k_layers<<<LBT, 256>>>(W, tails, out);
}

// round 5
// speedup vs baseline: 2.1934x; 1.0795x over previous
#include <cuda_runtime.h>
#include <cstdint>

#define PB 32
#define PS 1024
#define PNODE 256
#define PDEP 64
#define PR 50
#define PL 16
#define PE 128
#define PF 320
#define NEDGE (PB * PE)     // 4096
#define NTOT (PL * NEDGE)   // 65536
#define NGRP 4
#define GB (PB / NGRP)      // 8 batches / group
#define RB PR               // 50 blocks / group
#define LBT (NGRP * RB)     // 200 chain blocks
#define MAXCHUNK 640
#define PREPB 64

// ---------------- scratch --------------------------------------------------
__device__ float g_child[PB * PS * PDEP];
__device__ float g_msg[NEDGE * PDEP];
__device__ float g_pmsg[PL * NEDGE * PDEP];
__device__ int   g_gsort[NTOT];
__device__ int   g_gcnt[PR];
__device__ int   g_gbase[PR + 1];
__device__ int   g_gcur[PR];
__device__ int   g_chunk_rel[MAXCHUNK];
__device__ int   g_chunk_start[MAXCHUNK];
__device__ int   g_chunk_ne[MAXCHUNK];
__device__ int   g_nchunks;
__device__ unsigned int g_ticket;
__device__ int   g_rsortg[NGRP * PL * 1024];
__device__ int   g_rel_offg[NGRP * PL * (PR + 1)];
__device__ int   g_hkey[NTOT];
__device__ int   g_hidx[NTOT];
__device__ unsigned int g_bar4[NGRP];
__device__ unsigned int g_pbar;

// ---------------- f32x2 helpers -------------------------------------------
__device__ __forceinline__ void fma2(unsigned long long& acc,
                                     unsigned long long a, unsigned long long b) {
    asm("fma.rn.f32x2 %0, %1, %2, %0;" : "+l"(acc) : "l"(a), "l"(b));
}
__device__ __forceinline__ float hsum2(unsigned long long v) {
    unsigned int lo, hi;
    asm("mov.b64 {%0,%1}, %2;" : "=r"(lo), "=r"(hi) : "l"(v));
    return __uint_as_float(lo) + __uint_as_float(hi);
}

// ---------------- launch 0: init -------------------------------------------
__global__ void k_init(const float* __restrict__ ctx, float* __restrict__ out) {
    if (blockIdx.x == 0) {
        if (threadIdx.x == 0) { g_ticket = 0; g_pbar = 0; }
        if (threadIdx.x < NGRP) g_bar4[threadIdx.x] = 0;
        if (threadIdx.x < PR) g_gcnt[threadIdx.x] = 0;
    }
    const int64_t n_ctx = (int64_t)PB * PS * (PNODE / 4);
    const int64_t n_chd = (int64_t)PB * PS * (PDEP / 4);
    const int64_t total = n_ctx + n_chd;
    int64_t stride = (int64_t)gridDim.x * blockDim.x;
    for (int64_t i = (int64_t)blockIdx.x * blockDim.x + threadIdx.x; i < total; i += stride) {
        if (i < n_ctx) {
            int64_t row = i >> 6, d4 = i & 63;
            float4 v = ((const float4*)ctx)[i];
            *(float4*)&out[row * PF + d4 * 4] = v;
        } else {
            ((float4*)g_child)[i - n_ctx] = make_float4(0.f, 0.f, 0.f, 0.f);
        }
    }
}

// ---------------- prep barrier (64 co-resident blocks) ---------------------
__device__ __forceinline__ void psync(int* pc) {
    __syncthreads();
    (*pc)++;
    if (threadIdx.x == 0) {
        __threadfence();
        atomicAdd(&g_pbar, 1);
        unsigned int target = (unsigned int)(PREPB * (*pc));
        while (*(volatile unsigned int*)&g_pbar < target) { }
        __threadfence();
    }
    __syncthreads();
}

// ---------------- launch 1: all preprocessing, one kernel ------------------
__global__ void __launch_bounds__(256, 2)
k_prep(const int* __restrict__ rels, const int* __restrict__ heads) {
    int bid = blockIdx.x;
    int tid = threadIdx.x;
    __shared__ int cnt[PR];
    __shared__ int cnt2[PR], cur2[PR];
    __shared__ int hs2[2][128];
    __shared__ int sb[PR], sch[PR];
    int pc = 0;

    // --- A1: global rel histogram (this block's 1024 edges) ---
    if (tid < PR) { cnt[tid] = 0; cnt2[tid] = 0; }
    __syncthreads();
    int ebase = bid * 1024;
    #pragma unroll
    for (int t = 0; t < 4; t++)
        atomicAdd(&cnt[rels[ebase + tid + t * 256]], 1);
    __syncthreads();
    if (tid < PR && cnt[tid] > 0) atomicAdd(&g_gcnt[tid], cnt[tid]);

    // --- A2: per (group,layer) rel bucketing; bid = g*16 + l ---
    {
        int g = bid >> 4, l = bid & 15;
        #pragma unroll
        for (int t = 0; t < 4; t++) {
            int i = tid + t * 256;
            int b = g * GB + (i >> 7), e = i & 127;
            atomicAdd(&cnt2[rels[b * (PL * PE) + l * PE + e]], 1);
        }
        __syncthreads();
        if (tid == 0) {
            int s = 0;
            int ob = (g * PL + l) * (PR + 1);
            for (int r = 0; r < PR; r++) {
                g_rel_offg[ob + r] = s;
                cur2[r] = s;
                s += cnt2[r];
            }
            g_rel_offg[ob + PR] = s;
        }
        __syncthreads();
        #pragma unroll
        for (int t = 0; t < 4; t++) {
            int i = tid + t * 256;
            int b = g * GB + (i >> 7), e = i & 127;
            int r = rels[b * (PL * PE) + l * PE + e];
            int pos = atomicAdd(&cur2[r], 1);
            g_rsortg[(g * PL + l) * 1024 + pos] = (b << 7) | e;
        }
    }

    // --- A3: head rank-sort; 8 (l,b) tasks per block, 2 at a time ---
    #pragma unroll
    for (int t = 0; t < 4; t++) {
        int task = bid * 8 + t * 2 + (tid >> 7);  // 0..511
        int l = task >> 5, b = task & 31;
        int e = tid & 127;
        int h = heads[b * (PL * PE) + l * PE + e];
        hs2[tid >> 7][e] = h;
        __syncthreads();
        int rank = 0;
        #pragma unroll 8
        for (int o = 0; o < PE; o++) {
            int ho = hs2[tid >> 7][o];
            rank += (ho < h) || (ho == h && o < e);
        }
        int base = l * NEDGE + b * PE;
        g_hkey[base + rank] = h;
        g_hidx[base + rank] = e;
        __syncthreads();
    }

    psync(&pc);

    // --- B: prefix + chunk worklist (block 0) ---
    if (bid == 0) {
        if (tid == 0) {
            int s = 0, nc = 0;
            for (int r = 0; r < PR; r++) {
                sb[r] = s;
                sch[r] = nc;
                int c = g_gcnt[r];
                s += c;
                nc += (c + 127) >> 7;
            }
            g_gbase[PR] = s;
            g_nchunks = nc;
        }
        __syncthreads();
        if (tid < PR) {
            int b0 = sb[tid];
            g_gbase[tid] = b0;
            g_gcur[tid] = b0;
            int c = g_gcnt[tid];
            int nc0 = sch[tid];
            for (int o = 0, k = 0; o < c; o += 128, k++) {
                g_chunk_rel[nc0 + k] = tid;
                g_chunk_start[nc0 + k] = b0 + o;
                g_chunk_ne[nc0 + k] = min(128, c - o);
            }
        }
    }

    psync(&pc);

    // --- C: global scatter with per-block range reservation ---
    __shared__ int rbase[PR], rcur[PR];
    if (tid < PR) { rcur[tid] = 0; }
    __syncthreads();
    if (tid < PR) rbase[tid] = (cnt[tid] > 0) ? atomicAdd(&g_gcur[tid], cnt[tid]) : 0;
    __syncthreads();
    #pragma unroll
    for (int t = 0; t < 4; t++) {
        int idx = ebase + tid + t * 256;
        int r = rels[idx];
        int pos = rbase[r] + atomicAdd(&rcur[r], 1);
        int b = idx >> 11, l = (idx >> 7) & 15, e = idx & 127;
        g_gsort[pos] = (l << 12) | (b << 7) | e;
    }
}

// ---------------- launch 2: pmsg (ticket queue, unchanged core) ------------
#define PM_STRIDE 260
#define PM_SMEM ((64 * PM_STRIDE + 128 * PM_STRIDE) * (int)sizeof(float))

__global__ void __launch_bounds__(256, 1)
k_pmsg(const float* __restrict__ ctx, const float* __restrict__ W,
       const int* __restrict__ tails) {
    extern __shared__ float sm[];
    float* Ws = sm;                        // [64][260]
    float* Fs = sm + 64 * PM_STRIDE;       // [128][260]
    __shared__ int seid[128];
    __shared__ int stail[128];
    __shared__ int s_chunk;
    int tid = threadIdx.x;

    while (true) {
        if (tid == 0) s_chunk = atomicAdd(&g_ticket, 1);
        __syncthreads();
        int c = s_chunk;
        if (c >= g_nchunks) break;
        int r = g_chunk_rel[c];
        int start = g_chunk_start[c];
        int ne = g_chunk_ne[c];

        if (tid < 128) {
            int v = (tid < ne) ? g_gsort[start + tid] : -1;
            seid[tid] = v;
            int tnode = 0;
            if (v >= 0) {
                int b = (v >> 7) & 31, l = v >> 12, e = v & 127;
                tnode = b * PS + tails[b * (PL * PE) + l * PE + e];
            }
            stail[tid] = tnode;
        }
        const float* Wg = W + (int64_t)r * PDEP * PF;
        #pragma unroll
        for (int t = 0; t < 16; t++) {
            int idx = tid + t * 256;
            int k = idx >> 6, cc = idx & 63;
            *(float4*)&Ws[k * PM_STRIDE + cc * 4] = *(const float4*)&Wg[k * PF + cc * 4];
        }
        __syncthreads();

        #pragma unroll
        for (int t = 0; t < 32; t++) {
            int idx = tid + t * 256;
            int row = idx >> 6, cc = idx & 63;
            float4 v = make_float4(0.f, 0.f, 0.f, 0.f);
            if (seid[row] >= 0)
                v = *(const float4*)&ctx[(int64_t)stail[row] * PNODE + cc * 4];
            *(float4*)&Fs[row * PM_STRIDE + cc * 4] = v;
        }
        __syncthreads();

        int eg = tid & 31;
        int kg = tid >> 5;
        unsigned long long acc[4][8];
        #pragma unroll
        for (int i = 0; i < 4; i++)
            #pragma unroll
            for (int j = 0; j < 8; j++) acc[i][j] = 0ull;

        #pragma unroll 4
        for (int d = 0; d < PNODE; d += 4) {
            ulonglong2 w[8];
            #pragma unroll
            for (int j = 0; j < 8; j++)
                w[j] = *(const ulonglong2*)&Ws[(kg + 8 * j) * PM_STRIDE + d];
            #pragma unroll
            for (int i = 0; i < 4; i++) {
                ulonglong2 f = *(const ulonglong2*)&Fs[(eg + 32 * i) * PM_STRIDE + d];
                #pragma unroll
                for (int j = 0; j < 8; j++) {
                    fma2(acc[i][j], f.x, w[j].x);
                    fma2(acc[i][j], f.y, w[j].y);
                }
            }
        }

        #pragma unroll
        for (int i = 0; i < 4; i++) {
            int v = seid[eg + 32 * i];
            if (v >= 0) {
                int l = v >> 12, edge = v & 4095;
                float* dst = &g_pmsg[((int64_t)l * NEDGE + edge) * PDEP];
                #pragma unroll
                for (int j = 0; j < 8; j++)
                    dst[kg + 8 * j] = hsum2(acc[i][j]);
            }
        }
        __syncthreads();
    }
}

// ---------------- split group barrier --------------------------------------
__device__ __forceinline__ void g_arrive(int g, int* calls) {
    __syncthreads();
    (*calls)++;
    if (threadIdx.x == 0) {
        __threadfence();
        atomicAdd(&g_bar4[g], 1);
    }
}
__device__ __forceinline__ void g_wait(int g, int calls) {
    if (threadIdx.x == 0) {
        unsigned int target = (unsigned int)(RB * calls);
        while (*(volatile unsigned int*)&g_bar4[g] < target) { }
        __threadfence();
    }
    __syncthreads();
}

// ---------------- launch 3: persistent chain -------------------------------
__global__ void __launch_bounds__(256, 2)
k_layers(const float* __restrict__ W, const int* __restrict__ tails,
         float* __restrict__ out) {
    int bid = blockIdx.x;
    int g = bid / RB, r = bid - g * RB;
    __shared__ float Wc[64 * 68];
    __shared__ float Cs[64 * 68];
    __shared__ int seids[64];
    __shared__ int stls[64];
    int tid = threadIdx.x;
    int wid = tid >> 5, lane = tid & 31;
    int gw = r * 8 + wid;                      // 0..399 warp id in group

    // stage full W2[r] once
    {
        const float* Wg = W + (int64_t)r * PDEP * PF + PNODE;
        #pragma unroll
        for (int t = 0; t < 4; t++) {
            int idx = tid + t * 256;
            int k = idx >> 4, c = idx & 15;
            *(float4*)&Wc[k * 68 + c * 4] = *(const float4*)&Wg[k * PF + c * 4];
        }
    }
    // prefetch layer-0 tile-0 staging
    if (tid < 64) {
        int off0 = g_rel_offg[(g * PL) * (PR + 1) + r];
        int end0 = g_rel_offg[(g * PL) * (PR + 1) + r + 1];
        int v = -1, tn = 0;
        if (off0 + tid < end0) {
            v = g_rsortg[(g * PL) * 1024 + off0 + tid];
            int b = v >> 7, e = v & 127;
            tn = b * PS + tails[b * (PL * PE) + e];
        }
        seids[tid] = v;
        stls[tid] = tn;
    }
    __syncthreads();

    int calls = 0;
    for (int l = 0; l < PL; l++) {
        // ================= phase 1: messages for this rel ==================
        int ob = (g * PL + l) * (PR + 1);
        int off = g_rel_offg[ob + r];
        int end = g_rel_offg[ob + r + 1];
        for (int s = off; s < end; s += 64) {
            int ne = min(64, end - s);
            if (s > off) {   // tile 0 was prefetched
                __syncthreads();
                if (tid < 64) {
                    int v = -1, tn = 0;
                    if (tid < ne) {
                        v = g_rsortg[(g * PL + l) * 1024 + s + tid];
                        int b = v >> 7, e = v & 127;
                        tn = b * PS + tails[b * (PL * PE) + l * PE + e];
                    }
                    seids[tid] = v;
                    stls[tid] = tn;
                }
                __syncthreads();
            }
            if (l > 0) {
                #pragma unroll
                for (int t = 0; t < 4; t++) {
                    int idx = tid + t * 256;
                    int row = idx >> 4, c = idx & 15;
                    float4 v = make_float4(0.f, 0.f, 0.f, 0.f);
                    if (seids[row] >= 0)
                        v = __ldcg((const float4*)&g_child[stls[row] * PDEP + c * 4]);
                    *(float4*)&Cs[row * 68 + c * 4] = v;
                }
                __syncthreads();
            }

            int eg = tid & 15, kg = tid >> 4;
            float pm[4][4];
            #pragma unroll
            for (int i = 0; i < 4; i++) {
                int edge = seids[eg + 16 * i];
                #pragma unroll
                for (int j = 0; j < 4; j++) pm[i][j] = 0.f;
                if (edge >= 0) {
                    const float* p = &g_pmsg[((int64_t)l * NEDGE + edge) * PDEP];
                    #pragma unroll
                    for (int j = 0; j < 4; j++)
                        pm[i][j] = __ldcg(&p[kg + 16 * j]);
                }
            }
            unsigned long long acc[4][4];
            #pragma unroll
            for (int i = 0; i < 4; i++)
                #pragma unroll
                for (int j = 0; j < 4; j++) acc[i][j] = 0ull;
            if (l > 0) {
                #pragma unroll
                for (int d = 0; d < PDEP; d += 4) {
                    ulonglong2 w[4];
                    #pragma unroll
                    for (int j = 0; j < 4; j++)
                        w[j] = *(const ulonglong2*)&Wc[(kg + 16 * j) * 68 + d];
                    #pragma unroll
                    for (int i = 0; i < 4; i++) {
                        ulonglong2 f = *(const ulonglong2*)&Cs[(eg + 16 * i) * 68 + d];
                        #pragma unroll
                        for (int j = 0; j < 4; j++) {
                            fma2(acc[i][j], f.x, w[j].x);
                            fma2(acc[i][j], f.y, w[j].y);
                        }
                    }
                }
            }
            #pragma unroll
            for (int i = 0; i < 4; i++) {
                int edge = seids[eg + 16 * i];
                if (edge >= 0) {
                    float* dst = &g_msg[edge * PDEP];
                    #pragma unroll
                    for (int j = 0; j < 4; j++)
                        __stcg(&dst[kg + 16 * j], hsum2(acc[i][j]) + pm[i][j]);
                }
            }
        }
        g_arrive(g, &calls);

        // --- gap 1: prefetch phase-2 hkey/hidx windows (static data) ---
        int pk[3], px[3], pv[3];
        #pragma unroll
        for (int u = 0; u < 3; u++) {
            int p = gw + 400 * u;
            pk[u] = -1; px[u] = 0; pv[u] = -1;
            if (p < 1024) {
                int bb = g * GB + (p >> 7), pos = p & 127;
                int base = l * NEDGE + bb * PE;
                if (pos + lane < PE) {
                    pk[u] = __ldg(&g_hkey[base + pos + lane]);
                    px[u] = __ldg(&g_hidx[base + pos + lane]);
                }
                if (lane == 0 && pos > 0) pv[u] = __ldg(&g_hkey[base + pos - 1]);
            }
        }
        g_wait(g, calls);

        // ================= phase 2: scatter-average (warp/segment) =========
        #pragma unroll
        for (int u = 0; u < 3; u++) {
            int p = gw + 400 * u;
            if (p >= 1024) break;
            int bb = g * GB + (p >> 7), pos = p & 127;
            int head0 = __shfl_sync(0xffffffffu, pk[u], 0);
            int prev  = __shfl_sync(0xffffffffu, pv[u], 0);
            if (prev == head0) continue;       // not a segment start
            unsigned m = __ballot_sync(0xffffffffu, pk[u] == head0);
            int len = (m == 0xffffffffu) ? 32 : (__ffs(~m) - 1);
            int base = l * NEDGE + bb * PE;
            if (m == 0xffffffffu)
                while (pos + len < PE && __ldg(&g_hkey[base + pos + len]) == head0) len++;
            float s0 = 0.f, s1 = 0.f;
            for (int j = 0; j < len; j++) {
                int e = (j < 32) ? __shfl_sync(0xffffffffu, px[u], j)
                                 : __ldg(&g_hidx[base + pos + j]);
                const float* mm = &g_msg[(bb * PE + e) * PDEP];
                s0 += __ldcg(&mm[lane]);
                s1 += __ldcg(&mm[lane + 32]);
            }
            float inv = 1.f / (float)len;
            float* c = &g_child[(bb * PS + head0) * PDEP];
            __stcg(&c[lane], s0 * inv);
            __stcg(&c[lane + 32], s1 * inv);
        }
        g_arrive(g, &calls);

        // --- gap 2: prefetch next layer's tile-0 staging into smem ---
        if (l + 1 < PL && tid < 64) {
            int obn = (g * PL + l + 1) * (PR + 1);
            int offn = g_rel_offg[obn + r];
            int endn = g_rel_offg[obn + r + 1];
            int v = -1, tn = 0;
            if (offn + tid < endn) {
                v = g_rsortg[(g * PL + l + 1) * 1024 + offn + tid];
                int b = v >> 7, e = v & 127;
                tn = b * PS + tails[b * (PL * PE) + (l + 1) * PE + e];
            }
            seids[tid] = v;
            stls[tid] = tn;
        }
        g_wait(g, calls);
    }

    // ---- out[:, :, 256:320] for this group's 8 batches ----
    for (int idx = r * 256 + tid; idx < GB * PS * 16; idx += RB * 256) {
        int row = idx >> 4, c = idx & 15;
        int b = g * GB + (row >> 10), s = row & 1023;
        float4 v;
        v.x = __ldcg(&g_child[(b * PS + s) * PDEP + c * 4 + 0]);
        v.y = __ldcg(&g_child[(b * PS + s) * PDEP + c * 4 + 1]);
        v.z = __ldcg(&g_child[(b * PS + s) * PDEP + c * 4 + 2]);
        v.w = __ldcg(&g_child[(b * PS + s) * PDEP + c * 4 + 3]);
        *(float4*)&out[((int64_t)(b * PS + s)) * PF + PNODE + c * 4] = v;
    }
}

// ---------------------------------------------------------------------------
extern "C" void kernel_launch(void* const* d_in, const int* in_sizes, int n_in,
                              void* d_out, int out_size) {
    const float* ctx   = (const float*)d_in[0];
    const float* W     = (const float*)d_in[1];
    const int*   heads = (const int*)d_in[2];
    const int*   tails = (const int*)d_in[3];
    const int*   rels  = (const int*)d_in[4];
    float*       out   = (float*)d_out;

    cudaFuncSetAttribute(k_pmsg, cudaFuncAttributeMaxDynamicSharedMemorySize, PM_SMEM);

    k_init<<<2048, 256>>>(ctx, out);            // launch 0
    k_prep<<<PREPB, 256>>>(rels, heads);        // launch 1
    k_pmsg<<<148, 256, PM_SMEM>>>(ctx, W, tails);  // launch 2
    k_layers<<<LBT, 256>>>(W, tails, out);      // launch 3 (ncu-captured slot)
}